// round 15
// baseline (speedup 1.0000x reference)
#include <cuda_runtime.h>
#include <cuda_bf16.h>
#include <stdint.h>

// out_f32[4096, 4096] = bf16round( x_bf16[4096,4096] @ W_bf16[4096,4096]^T + bias )
// d_out dtype is FLOAT32 (bf16 values widened).
#define TOKENS 4096
#define KDIM   4096
#define NDIM   4096

// 128x128 CTA tile, BK=64, 8 warps (4m x 2n), warp tile 32x64, 3 stages,
// 2 CTA/SM, persistent CTAs, single barrier per K-chunk. cp.async issue for
// chunk c+2 is placed INSIDE the LDSM->MMA RAW latency window of ks=0/ks=1.
#define BM 128
#define BN 128
#define BK 64
#define KT_PER_TILE (KDIM / BK)       // 64
#define N_TILES ((TOKENS / BM) * (NDIM / BN))   // 1024
#define GRID_P 304                    // 2 per SM on 152 SMs
#define STAGES 3
#define A_STAGE 16384                 // 128 rows x 128B
#define STAGE_BYTES 32768             // A 16K + B 16K
#define SMEM_TOTAL (STAGES * STAGE_BYTES)   // 98304 -> 2 CTAs/SM

// Scratch: pre-converted bf16 operands (__device__ globals; no allocs)
__device__ __align__(256) __nv_bfloat16 g_x[(size_t)TOKENS * KDIM];
__device__ __align__(256) __nv_bfloat16 g_w[(size_t)NDIM * KDIM];

// ---------------- helpers ----------------
static __device__ __forceinline__ uint32_t smem_u32(const void* p) {
    uint32_t a;
    asm("{ .reg .u64 t; cvta.to.shared.u64 t, %1; cvt.u32.u64 %0, t; }" : "=r"(a) : "l"(p));
    return a;
}
static __device__ __forceinline__ void cp_async16(uint32_t smem_dst, uint64_t gsrc) {
    asm volatile("cp.async.cg.shared.global [%0], [%1], 16;"
                 :: "r"(smem_dst), "l"(gsrc) : "memory");
}
static __device__ __forceinline__ uint32_t pack_bf162(float a, float b) {
    __nv_bfloat162 p;
    p.x = __float2bfloat16(a); p.y = __float2bfloat16(b);
    return *reinterpret_cast<uint32_t*>(&p);
}

// ---------------- fused conversion kernel (MLP=4 per iteration) ----------------
// Each loop iteration produces TWO uint4 outputs (16 bf16) and fronts all four
// LDG.128 loads before converting, so 4 independent DRAM loads are in flight.
#define X_U4 ((size_t)TOKENS * KDIM / 8)   // uint4 outputs for g_x
#define W_U4 ((size_t)NDIM * KDIM / 8)
__global__ void cvt_all_kernel(const float* __restrict__ x,
                               const float* __restrict__ w,
                               const float* __restrict__ scale) {
    const size_t nthr = (size_t)gridDim.x * blockDim.x;
    const size_t gtid = (size_t)blockIdx.x * blockDim.x + threadIdx.x;
    const float4* __restrict__ x4 = reinterpret_cast<const float4*>(x);
    const float4* __restrict__ w4 = reinterpret_cast<const float4*>(w);
    uint4* __restrict__ ox = reinterpret_cast<uint4*>(g_x);
    uint4* __restrict__ ow = reinterpret_cast<uint4*>(g_w);

    // ---- x region: pairs of uint4 outputs ----
    for (size_t p = gtid; p < X_U4 / 2; p += nthr) {
        const size_t i = 2 * p;
        float4 v0 = __ldg(&x4[2 * i]);
        float4 v1 = __ldg(&x4[2 * i + 1]);
        float4 v2 = __ldg(&x4[2 * i + 2]);
        float4 v3 = __ldg(&x4[2 * i + 3]);
        uint4 o0, o1;
        o0.x = pack_bf162(v0.x, v0.y); o0.y = pack_bf162(v0.z, v0.w);
        o0.z = pack_bf162(v1.x, v1.y); o0.w = pack_bf162(v1.z, v1.w);
        o1.x = pack_bf162(v2.x, v2.y); o1.y = pack_bf162(v2.z, v2.w);
        o1.z = pack_bf162(v3.x, v3.y); o1.w = pack_bf162(v3.z, v3.w);
        ox[i] = o0;
        ox[i + 1] = o1;
    }
    // ---- w region ----
    for (size_t p = gtid; p < W_U4 / 2; p += nthr) {
        const size_t j = 2 * p;                 // both outputs in same row
        const int row = (int)(j >> 9);          // j*8 / 4096
        // reference: bf16(fp8_val) * bf16(scale) in bf16; fp8 vals exact in
        // f32, so f32 multiply + single bf16 round is identical.
        const float s = __bfloat162float(__float2bfloat16(__ldg(&scale[row])));
        float4 v0 = __ldg(&w4[2 * j]);
        float4 v1 = __ldg(&w4[2 * j + 1]);
        float4 v2 = __ldg(&w4[2 * j + 2]);
        float4 v3 = __ldg(&w4[2 * j + 3]);
        uint4 o0, o1;
        o0.x = pack_bf162(v0.x * s, v0.y * s); o0.y = pack_bf162(v0.z * s, v0.w * s);
        o0.z = pack_bf162(v1.x * s, v1.y * s); o0.w = pack_bf162(v1.z * s, v1.w * s);
        o1.x = pack_bf162(v2.x * s, v2.y * s); o1.y = pack_bf162(v2.z * s, v2.w * s);
        o1.z = pack_bf162(v3.x * s, v3.y * s); o1.w = pack_bf162(v3.z * s, v3.w * s);
        ow[j] = o0;
        ow[j + 1] = o1;
    }
}

// ---------------- persistent mma.sync bf16 GEMM ----------------
__global__ void __launch_bounds__(256, 2)
fp8lin_gemm(const float* __restrict__ bias, float* __restrict__ out) {
    extern __shared__ char smem[];
    const uint32_t sb = smem_u32(smem);
    const int tid = threadIdx.x;
    const int wid = tid >> 5, lane = tid & 31;
    const int wm = wid >> 1, wn = wid & 1;         // 4x2 warp grid, warp tile 32x64
    const int bid = blockIdx.x;

    uint64_t baseA, baseB;
    {
        const void* pa = g_x;
        const void* pb = g_w;
        asm("cvta.to.global.u64 %0, %1;" : "=l"(baseA) : "l"(pa));
        asm("cvta.to.global.u64 %0, %1;" : "=l"(baseB) : "l"(pb));
    }

    const int ntiles = (N_TILES - 1 - bid) / GRID_P + 1;
    const int total_chunks = ntiles * KT_PER_TILE;

    // Per-thread constant loader offsets.
    const int lrow = tid >> 3, lch = tid & 7;
    const uint32_t sOffBase = ((uint32_t)lrow << 7) | (uint32_t)((lch << 4) ^ ((lrow & 7) << 4));
    const uint64_t gOffBase = (uint64_t)lrow * (KDIM * 2) + (uint64_t)(lch << 4);
    #define ROW_STRIDE_32 ((uint64_t)32 * KDIM * 2)

    auto load_chunk_A = [&](int c) {
        const int t = bid + (c >> 6) * GRID_P;
        const uint64_t gA = baseA + ((uint64_t)(t >> 5) << 20)
                          + (uint64_t)(c & 63) * 128 + gOffBase;
        const uint32_t sA = sb + (uint32_t)(c % STAGES) * STAGE_BYTES + sOffBase;
        #pragma unroll
        for (int it = 0; it < 4; ++it)
            cp_async16(sA + (uint32_t)(it << 12), gA + (uint64_t)it * ROW_STRIDE_32);
    };
    auto load_chunk_B = [&](int c) {
        const int t = bid + (c >> 6) * GRID_P;
        const uint64_t gB = baseB + ((uint64_t)(t & 31) << 20)
                          + (uint64_t)(c & 63) * 128 + gOffBase;
        const uint32_t sB = sb + (uint32_t)(c % STAGES) * STAGE_BYTES + A_STAGE + sOffBase;
        #pragma unroll
        for (int it = 0; it < 4; ++it)
            cp_async16(sB + (uint32_t)(it << 12), gB + (uint64_t)it * ROW_STRIDE_32);
        asm volatile("cp.async.commit_group;" ::: "memory");
    };

    // ldmatrix per-thread address components.
    const int j8 = lane >> 3, i8 = lane & 7;
    uint32_t aP[2], aX[2];
    #pragma unroll
    for (int mt = 0; mt < 2; ++mt) {
        int r = wm * 32 + mt * 16 + (j8 & 1) * 8 + i8;
        aP[mt] = (uint32_t)r << 7;
        aX[mt] = (uint32_t)((r & 7) << 4);
    }
    const uint32_t aK = (uint32_t)((j8 >> 1) << 4);
    uint32_t bP[4], bX[4];
    #pragma unroll
    for (int g = 0; g < 4; ++g) {
        int r = wn * 64 + g * 16 + ((j8 >> 1) & 1) * 8 + i8;
        bP[g] = (uint32_t)r << 7;
        bX[g] = (uint32_t)((r & 7) << 4);
    }
    const uint32_t bK = (uint32_t)((j8 & 1) << 4);

    float acc[2][8][4];
    #pragma unroll
    for (int mt = 0; mt < 2; ++mt)
        #pragma unroll
        for (int nt = 0; nt < 8; ++nt)
            #pragma unroll
            for (int q = 0; q < 4; ++q) acc[mt][nt][q] = 0.0f;

    const int g4 = lane >> 2, tig = lane & 3;

    load_chunk_A(0); load_chunk_B(0);
    load_chunk_A(1); load_chunk_B(1);

    #pragma unroll 1
    for (int c = 0; c < total_chunks; ++c) {
        // Committed groups: 0..c+1. wait_group 1 -> group c complete.
        if (c + 1 < total_chunks) {
            asm volatile("cp.async.wait_group 1;" ::: "memory");
        } else {
            asm volatile("cp.async.wait_group 0;" ::: "memory");
        }
        // Single barrier: publishes chunk c AND proves stage (c+2)%3 == (c-1)%3
        // drained by all warps.
        __syncthreads();

        const uint32_t sA = sb + (uint32_t)(c % STAGES) * STAGE_BYTES;
        const uint32_t sB = sA + A_STAGE;
        const bool more = (c + 2 < total_chunks);

        #pragma unroll
        for (int ks = 0; ks < 4; ++ks) {
            const uint32_t kb = (uint32_t)(ks << 5);
            uint32_t a[2][4], b[4][4];
            #pragma unroll
            for (int mt = 0; mt < 2; ++mt) {
                uint32_t addr = sA + aP[mt] + ((kb + aK) ^ aX[mt]);
                asm volatile("ldmatrix.sync.aligned.m8n8.x4.shared.b16 {%0,%1,%2,%3}, [%4];"
                             : "=r"(a[mt][0]), "=r"(a[mt][1]), "=r"(a[mt][2]), "=r"(a[mt][3])
                             : "r"(addr));
            }
            #pragma unroll
            for (int g = 0; g < 4; ++g) {
                uint32_t addr = sB + bP[g] + ((kb + bK) ^ bX[g]);
                asm volatile("ldmatrix.sync.aligned.m8n8.x4.shared.b16 {%0,%1,%2,%3}, [%4];"
                             : "=r"(b[g][0]), "=r"(b[g][1]), "=r"(b[g][2]), "=r"(b[g][3])
                             : "r"(addr));
            }
            // cp.async issue for chunk c+2 goes HERE — inside the ~29-cyc
            // LDSM->MMA RAW window. volatile-asm ordering pins the placement:
            // the LSU issues these while the first MMA waits on its fragments.
            if (ks == 0 && more) load_chunk_A(c + 2);
            if (ks == 1 && more) load_chunk_B(c + 2);   // + commit_group
            #pragma unroll
            for (int mt = 0; mt < 2; ++mt) {
                #pragma unroll
                for (int nt = 0; nt < 8; ++nt) {
                    const uint32_t b0 = b[nt >> 1][(nt & 1) * 2];
                    const uint32_t b1 = b[nt >> 1][(nt & 1) * 2 + 1];
                    asm volatile(
                        "mma.sync.aligned.m16n8k16.row.col.f32.bf16.bf16.f32 "
                        "{%0,%1,%2,%3}, {%4,%5,%6,%7}, {%8,%9}, {%0,%1,%2,%3};"
                        : "+f"(acc[mt][nt][0]), "+f"(acc[mt][nt][1]),
                          "+f"(acc[mt][nt][2]), "+f"(acc[mt][nt][3])
                        : "r"(a[mt][0]), "r"(a[mt][1]), "r"(a[mt][2]), "r"(a[mt][3]),
                          "r"(b0), "r"(b1));
                }
            }
        }

        // ---- tile boundary: epilogue (registers + gmem only; no barrier).
        if ((c & 63) == 63) {
            const int t = bid + (c >> 6) * GRID_P;
            const int m0 = (t >> 5) * BM, n0 = (t & 31) * BN;
            #pragma unroll
            for (int nt = 0; nt < 8; ++nt) {
                const int col = n0 + wn * 64 + nt * 8 + tig * 2;
                const __nv_bfloat16 bz0 = __float2bfloat16(__ldg(&bias[col]));
                const __nv_bfloat16 bz1 = __float2bfloat16(__ldg(&bias[col + 1]));
                #pragma unroll
                for (int mt = 0; mt < 2; ++mt) {
                    const int r0 = m0 + wm * 32 + mt * 16 + g4;
                    float2 v0, v1;
                    v0.x = __bfloat162float(__hadd(__float2bfloat16(acc[mt][nt][0]), bz0));
                    v0.y = __bfloat162float(__hadd(__float2bfloat16(acc[mt][nt][1]), bz1));
                    v1.x = __bfloat162float(__hadd(__float2bfloat16(acc[mt][nt][2]), bz0));
                    v1.y = __bfloat162float(__hadd(__float2bfloat16(acc[mt][nt][3]), bz1));
                    *reinterpret_cast<float2*>(out + (size_t)r0 * NDIM + col) = v0;
                    *reinterpret_cast<float2*>(out + (size_t)(r0 + 8) * NDIM + col) = v1;
                    acc[mt][nt][0] = 0.0f; acc[mt][nt][1] = 0.0f;
                    acc[mt][nt][2] = 0.0f; acc[mt][nt][3] = 0.0f;
                }
            }
        }
    }
}

// ---------------- launch ----------------
extern "C" void kernel_launch(void* const* d_in, const int* in_sizes, int n_in,
                              void* d_out, int out_size) {
    const float* x     = (const float*)d_in[0];   // [2,2048,4096] f32
    const float* w     = (const float*)d_in[1];   // [4096,4096] f32 (fp8-representable)
    const float* scale = (const float*)d_in[2];   // [4096,1] f32
    const float* bias  = (const float*)d_in[3];   // [4096] f32
    float* out         = (float*)d_out;           // [2,2048,4096] f32 (bf16 values widened)

    cudaFuncSetAttribute(fp8lin_gemm, cudaFuncAttributeMaxDynamicSharedMemorySize, SMEM_TOTAL);

    cvt_all_kernel<<<4096, 256>>>(x, w, scale);

    fp8lin_gemm<<<GRID_P, 256, SMEM_TOTAL>>>(bias, out);
}

// round 16
// speedup vs baseline: 1.0272x; 1.0272x over previous
#include <cuda_runtime.h>
#include <cuda_bf16.h>
#include <stdint.h>

// out_f32[4096, 4096] = bf16round( x_bf16[4096,4096] @ W_bf16[4096,4096]^T + bias )
// d_out dtype is FLOAT32 (bf16 values widened).
#define TOKENS 4096
#define KDIM   4096
#define NDIM   4096

// R14 GEMM (best: tensor 76.2%): 128x128 CTA tile, BK=64, 8 warps (4m x 2n),
// warp tile 32x64, 3 stages, 2 CTA/SM, persistent CTAs, single barrier per
// K-chunk, cp.async issue for chunk c+2 deferred until AFTER the ks=0/ks=1 MMA
// blocks (tensor pipe has 16 MMAs queued; LSU issue hides behind them).
#define BM 128
#define BN 128
#define BK 64
#define KT_PER_TILE (KDIM / BK)       // 64
#define N_TILES ((TOKENS / BM) * (NDIM / BN))   // 1024
#define GRID_P 304                    // 2 per SM on 152 SMs
#define STAGES 3
#define A_STAGE 16384                 // 128 rows x 128B
#define STAGE_BYTES 32768             // A 16K + B 16K
#define SMEM_TOTAL (STAGES * STAGE_BYTES)   // 98304 -> 2 CTAs/SM

// Scratch: pre-converted bf16 operands (__device__ globals; no allocs)
__device__ __align__(256) __nv_bfloat16 g_x[(size_t)TOKENS * KDIM];
__device__ __align__(256) __nv_bfloat16 g_w[(size_t)NDIM * KDIM];

// ---------------- helpers ----------------
static __device__ __forceinline__ uint32_t smem_u32(const void* p) {
    uint32_t a;
    asm("{ .reg .u64 t; cvta.to.shared.u64 t, %1; cvt.u32.u64 %0, t; }" : "=r"(a) : "l"(p));
    return a;
}
static __device__ __forceinline__ void cp_async16(uint32_t smem_dst, uint64_t gsrc) {
    asm volatile("cp.async.cg.shared.global [%0], [%1], 16;"
                 :: "r"(smem_dst), "l"(gsrc) : "memory");
}
static __device__ __forceinline__ uint32_t pack_bf162(float a, float b) {
    __nv_bfloat162 p;
    p.x = __float2bfloat16(a); p.y = __float2bfloat16(b);
    return *reinterpret_cast<uint32_t*>(&p);
}

// ---------------- fused conversion kernel (MLP=4 per iteration) ----------------
// Each loop iteration produces TWO uint4 outputs (16 bf16) and fronts all four
// LDG.128 loads before converting, so 4 independent DRAM loads are in flight.
#define X_U4 ((size_t)TOKENS * KDIM / 8)   // uint4 outputs for g_x
#define W_U4 ((size_t)NDIM * KDIM / 8)
__global__ void cvt_all_kernel(const float* __restrict__ x,
                               const float* __restrict__ w,
                               const float* __restrict__ scale) {
    const size_t nthr = (size_t)gridDim.x * blockDim.x;
    const size_t gtid = (size_t)blockIdx.x * blockDim.x + threadIdx.x;
    const float4* __restrict__ x4 = reinterpret_cast<const float4*>(x);
    const float4* __restrict__ w4 = reinterpret_cast<const float4*>(w);
    uint4* __restrict__ ox = reinterpret_cast<uint4*>(g_x);
    uint4* __restrict__ ow = reinterpret_cast<uint4*>(g_w);

    // ---- x region: pairs of uint4 outputs ----
    for (size_t p = gtid; p < X_U4 / 2; p += nthr) {
        const size_t i = 2 * p;
        float4 v0 = __ldg(&x4[2 * i]);
        float4 v1 = __ldg(&x4[2 * i + 1]);
        float4 v2 = __ldg(&x4[2 * i + 2]);
        float4 v3 = __ldg(&x4[2 * i + 3]);
        uint4 o0, o1;
        o0.x = pack_bf162(v0.x, v0.y); o0.y = pack_bf162(v0.z, v0.w);
        o0.z = pack_bf162(v1.x, v1.y); o0.w = pack_bf162(v1.z, v1.w);
        o1.x = pack_bf162(v2.x, v2.y); o1.y = pack_bf162(v2.z, v2.w);
        o1.z = pack_bf162(v3.x, v3.y); o1.w = pack_bf162(v3.z, v3.w);
        ox[i] = o0;
        ox[i + 1] = o1;
    }
    // ---- w region ----
    for (size_t p = gtid; p < W_U4 / 2; p += nthr) {
        const size_t j = 2 * p;                 // both outputs in same row
        const int row = (int)(j >> 9);          // j*8 / 4096
        // reference: bf16(fp8_val) * bf16(scale) in bf16; fp8 vals exact in
        // f32, so f32 multiply + single bf16 round is identical.
        const float s = __bfloat162float(__float2bfloat16(__ldg(&scale[row])));
        float4 v0 = __ldg(&w4[2 * j]);
        float4 v1 = __ldg(&w4[2 * j + 1]);
        float4 v2 = __ldg(&w4[2 * j + 2]);
        float4 v3 = __ldg(&w4[2 * j + 3]);
        uint4 o0, o1;
        o0.x = pack_bf162(v0.x * s, v0.y * s); o0.y = pack_bf162(v0.z * s, v0.w * s);
        o0.z = pack_bf162(v1.x * s, v1.y * s); o0.w = pack_bf162(v1.z * s, v1.w * s);
        o1.x = pack_bf162(v2.x * s, v2.y * s); o1.y = pack_bf162(v2.z * s, v2.w * s);
        o1.z = pack_bf162(v3.x * s, v3.y * s); o1.w = pack_bf162(v3.z * s, v3.w * s);
        ow[j] = o0;
        ow[j + 1] = o1;
    }
}

// ---------------- persistent mma.sync bf16 GEMM (R14 schedule) ----------------
__global__ void __launch_bounds__(256, 2)
fp8lin_gemm(const float* __restrict__ bias, float* __restrict__ out) {
    extern __shared__ char smem[];
    const uint32_t sb = smem_u32(smem);
    const int tid = threadIdx.x;
    const int wid = tid >> 5, lane = tid & 31;
    const int wm = wid >> 1, wn = wid & 1;         // 4x2 warp grid, warp tile 32x64
    const int bid = blockIdx.x;

    uint64_t baseA, baseB;
    {
        const void* pa = g_x;
        const void* pb = g_w;
        asm("cvta.to.global.u64 %0, %1;" : "=l"(baseA) : "l"(pa));
        asm("cvta.to.global.u64 %0, %1;" : "=l"(baseB) : "l"(pb));
    }

    const int ntiles = (N_TILES - 1 - bid) / GRID_P + 1;
    const int total_chunks = ntiles * KT_PER_TILE;

    // Per-thread constant loader offsets.
    const int lrow = tid >> 3, lch = tid & 7;
    const uint32_t sOffBase = ((uint32_t)lrow << 7) | (uint32_t)((lch << 4) ^ ((lrow & 7) << 4));
    const uint64_t gOffBase = (uint64_t)lrow * (KDIM * 2) + (uint64_t)(lch << 4);
    #define ROW_STRIDE_32 ((uint64_t)32 * KDIM * 2)

    auto load_chunk_A = [&](int c) {
        const int t = bid + (c >> 6) * GRID_P;
        const uint64_t gA = baseA + ((uint64_t)(t >> 5) << 20)
                          + (uint64_t)(c & 63) * 128 + gOffBase;
        const uint32_t sA = sb + (uint32_t)(c % STAGES) * STAGE_BYTES + sOffBase;
        #pragma unroll
        for (int it = 0; it < 4; ++it)
            cp_async16(sA + (uint32_t)(it << 12), gA + (uint64_t)it * ROW_STRIDE_32);
    };
    auto load_chunk_B = [&](int c) {
        const int t = bid + (c >> 6) * GRID_P;
        const uint64_t gB = baseB + ((uint64_t)(t & 31) << 20)
                          + (uint64_t)(c & 63) * 128 + gOffBase;
        const uint32_t sB = sb + (uint32_t)(c % STAGES) * STAGE_BYTES + A_STAGE + sOffBase;
        #pragma unroll
        for (int it = 0; it < 4; ++it)
            cp_async16(sB + (uint32_t)(it << 12), gB + (uint64_t)it * ROW_STRIDE_32);
        asm volatile("cp.async.commit_group;" ::: "memory");
    };

    // ldmatrix per-thread address components.
    const int j8 = lane >> 3, i8 = lane & 7;
    uint32_t aP[2], aX[2];
    #pragma unroll
    for (int mt = 0; mt < 2; ++mt) {
        int r = wm * 32 + mt * 16 + (j8 & 1) * 8 + i8;
        aP[mt] = (uint32_t)r << 7;
        aX[mt] = (uint32_t)((r & 7) << 4);
    }
    const uint32_t aK = (uint32_t)((j8 >> 1) << 4);
    uint32_t bP[4], bX[4];
    #pragma unroll
    for (int g = 0; g < 4; ++g) {
        int r = wn * 64 + g * 16 + ((j8 >> 1) & 1) * 8 + i8;
        bP[g] = (uint32_t)r << 7;
        bX[g] = (uint32_t)((r & 7) << 4);
    }
    const uint32_t bK = (uint32_t)((j8 & 1) << 4);

    float acc[2][8][4];
    #pragma unroll
    for (int mt = 0; mt < 2; ++mt)
        #pragma unroll
        for (int nt = 0; nt < 8; ++nt)
            #pragma unroll
            for (int q = 0; q < 4; ++q) acc[mt][nt][q] = 0.0f;

    const int g4 = lane >> 2, tig = lane & 3;

    load_chunk_A(0); load_chunk_B(0);
    load_chunk_A(1); load_chunk_B(1);

    #pragma unroll 1
    for (int c = 0; c < total_chunks; ++c) {
        // Committed groups: 0..c+1. wait_group 1 -> group c complete.
        if (c + 1 < total_chunks) {
            asm volatile("cp.async.wait_group 1;" ::: "memory");
        } else {
            asm volatile("cp.async.wait_group 0;" ::: "memory");
        }
        // Single barrier: publishes chunk c AND proves stage (c+2)%3 == (c-1)%3
        // drained by all warps.
        __syncthreads();

        const uint32_t sA = sb + (uint32_t)(c % STAGES) * STAGE_BYTES;
        const uint32_t sB = sA + A_STAGE;
        const bool more = (c + 2 < total_chunks);

        #pragma unroll
        for (int ks = 0; ks < 4; ++ks) {
            const uint32_t kb = (uint32_t)(ks << 5);
            uint32_t a[2][4], b[4][4];
            #pragma unroll
            for (int mt = 0; mt < 2; ++mt) {
                uint32_t addr = sA + aP[mt] + ((kb + aK) ^ aX[mt]);
                asm volatile("ldmatrix.sync.aligned.m8n8.x4.shared.b16 {%0,%1,%2,%3}, [%4];"
                             : "=r"(a[mt][0]), "=r"(a[mt][1]), "=r"(a[mt][2]), "=r"(a[mt][3])
                             : "r"(addr));
            }
            #pragma unroll
            for (int g = 0; g < 4; ++g) {
                uint32_t addr = sB + bP[g] + ((kb + bK) ^ bX[g]);
                asm volatile("ldmatrix.sync.aligned.m8n8.x4.shared.b16 {%0,%1,%2,%3}, [%4];"
                             : "=r"(b[g][0]), "=r"(b[g][1]), "=r"(b[g][2]), "=r"(b[g][3])
                             : "r"(addr));
            }
            #pragma unroll
            for (int mt = 0; mt < 2; ++mt) {
                #pragma unroll
                for (int nt = 0; nt < 8; ++nt) {
                    const uint32_t b0 = b[nt >> 1][(nt & 1) * 2];
                    const uint32_t b1 = b[nt >> 1][(nt & 1) * 2 + 1];
                    asm volatile(
                        "mma.sync.aligned.m16n8k16.row.col.f32.bf16.bf16.f32 "
                        "{%0,%1,%2,%3}, {%4,%5,%6,%7}, {%8,%9}, {%0,%1,%2,%3};"
                        : "+f"(acc[mt][nt][0]), "+f"(acc[mt][nt][1]),
                          "+f"(acc[mt][nt][2]), "+f"(acc[mt][nt][3])
                        : "r"(a[mt][0]), "r"(a[mt][1]), "r"(a[mt][2]), "r"(a[mt][3]),
                          "r"(b0), "r"(b1));
                }
            }
            // R14 placement: cp.async issue for chunk c+2 AFTER this ks's MMA
            // block — the tensor pipe chews on the 16 queued MMAs while the
            // LSU issues these (issue slots here are hidden, not critical-path).
            if (ks == 0 && more) load_chunk_A(c + 2);
            if (ks == 1 && more) load_chunk_B(c + 2);   // + commit_group
        }

        // ---- tile boundary: epilogue (registers + gmem only; no barrier).
        if ((c & 63) == 63) {
            const int t = bid + (c >> 6) * GRID_P;
            const int m0 = (t >> 5) * BM, n0 = (t & 31) * BN;
            #pragma unroll
            for (int nt = 0; nt < 8; ++nt) {
                const int col = n0 + wn * 64 + nt * 8 + tig * 2;
                const __nv_bfloat16 bz0 = __float2bfloat16(__ldg(&bias[col]));
                const __nv_bfloat16 bz1 = __float2bfloat16(__ldg(&bias[col + 1]));
                #pragma unroll
                for (int mt = 0; mt < 2; ++mt) {
                    const int r0 = m0 + wm * 32 + mt * 16 + g4;
                    float2 v0, v1;
                    v0.x = __bfloat162float(__hadd(__float2bfloat16(acc[mt][nt][0]), bz0));
                    v0.y = __bfloat162float(__hadd(__float2bfloat16(acc[mt][nt][1]), bz1));
                    v1.x = __bfloat162float(__hadd(__float2bfloat16(acc[mt][nt][2]), bz0));
                    v1.y = __bfloat162float(__hadd(__float2bfloat16(acc[mt][nt][3]), bz1));
                    *reinterpret_cast<float2*>(out + (size_t)r0 * NDIM + col) = v0;
                    *reinterpret_cast<float2*>(out + (size_t)(r0 + 8) * NDIM + col) = v1;
                    acc[mt][nt][0] = 0.0f; acc[mt][nt][1] = 0.0f;
                    acc[mt][nt][2] = 0.0f; acc[mt][nt][3] = 0.0f;
                }
            }
        }
    }
}

// ---------------- launch ----------------
extern "C" void kernel_launch(void* const* d_in, const int* in_sizes, int n_in,
                              void* d_out, int out_size) {
    const float* x     = (const float*)d_in[0];   // [2,2048,4096] f32
    const float* w     = (const float*)d_in[1];   // [4096,4096] f32 (fp8-representable)
    const float* scale = (const float*)d_in[2];   // [4096,1] f32
    const float* bias  = (const float*)d_in[3];   // [4096] f32
    float* out         = (float*)d_out;           // [2,2048,4096] f32 (bf16 values widened)

    cudaFuncSetAttribute(fp8lin_gemm, cudaFuncAttributeMaxDynamicSharedMemorySize, SMEM_TOTAL);

    cvt_all_kernel<<<4096, 256>>>(x, w, scale);

    fp8lin_gemm<<<GRID_P, 256, SMEM_TOTAL>>>(bias, out);
}